// round 6
// baseline (speedup 1.0000x reference)
#include <cuda_runtime.h>
#include <cuda_bf16.h>
#include <math.h>
#include <stdint.h>

#define N_NODES   8192
#define C_IN      256
#define C_OUT     128
#define NEG_SLOPE 0.2f
#define MAX_DEG   128

#define BM 32
#define BK 16
#define GEMM_BLOCKS (N_NODES / BM)     // 256
#define SCAN_BLOCKS 2048

// -------- scratch (__device__ globals; zero-initialized at module load) ----
__device__ float g_h[N_NODES * C_OUT];      // 4 MB, h = x @ W
__device__ float g_asrc[N_NODES];
__device__ float g_adst[N_NODES];
__device__ int   g_cnt[N_NODES];            // per-column degree (excl. self)
__device__ int   g_list[N_NODES * MAX_DEG]; // 4 MB, CSC row lists

// ---------------------------------------------------------------------
// Fused front kernel.
//  blocks [0, GEMM_BLOCKS):            h = x@W (4x4 micro-tile) + attn scores
//  blocks [GEMM_BLOCKS, +SCAN_BLOCKS): stream adj once, build CSC lists.
// Scan is SOFTWARE-PIPELINED: iteration k+1's 4 LDG.128 are issued before
// processing iteration k, so the atomicAdd->STG latency chains (~320cyc)
// overlap with loads already in flight instead of draining the mem pipe.
// launch_bounds(256,5): 51-reg budget fits 8 live uint4 without spills;
// 40 warps/SM x 2KB in flight = 80KB >> latency-BW product (~25KB).
// g_cnt is zeroed by the previous aggregate launch (zero-init at load).
// ---------------------------------------------------------------------
__global__ __launch_bounds__(256, 5) void fused_front_kernel(
    const float* __restrict__ x, const float* __restrict__ W,
    const float* __restrict__ adj,
    const float* __restrict__ att_src, const float* __restrict__ att_dst) {

    if (blockIdx.x >= GEMM_BLOCKS) {
        // ======= adjacency scan: prefetched batch-4 LDG.128 stream =======
        const uint4* a4 = reinterpret_cast<const uint4*>(adj);
        const int tid0   = (blockIdx.x - GEMM_BLOCKS) * 256 + threadIdx.x;
        const int stride = SCAN_BLOCKS * 256;           // 524288
        // total uint4 = 16777216 = 32*stride -> 8 iterations of batch-4

        int q = tid0;
        uint4 c0 = __ldcs(&a4[q]);
        uint4 c1 = __ldcs(&a4[q + stride]);
        uint4 c2 = __ldcs(&a4[q + 2 * stride]);
        uint4 c3 = __ldcs(&a4[q + 3 * stride]);

#pragma unroll
        for (int it = 0; it < 8; it++) {
            int qn = q + 4 * stride;
            uint4 n0 = make_uint4(0u, 0u, 0u, 0u), n1 = n0, n2 = n0, n3 = n0;
            if (it < 7) {                 // issue next batch BEFORE processing
                n0 = __ldcs(&a4[qn]);
                n1 = __ldcs(&a4[qn + stride]);
                n2 = __ldcs(&a4[qn + 2 * stride]);
                n3 = __ldcs(&a4[qn + 3 * stride]);
            }
            uint4 vv[4] = {c0, c1, c2, c3};
#pragma unroll
            for (int u = 0; u < 4; u++) {
                uint4 v = vv[u];
                if ((v.x | v.y | v.z | v.w) == 0u) continue;
                int Q  = q + u * stride;
                int i  = Q >> 11;                 // row (2048 uint4 per row)
                int j0 = (Q & 2047) << 2;         // first column of the 4
                unsigned int b[4] = {v.x, v.y, v.z, v.w};
#pragma unroll
                for (int t = 0; t < 4; t++) {
                    if (b[t] != 0u) {
                        int jj = j0 + t;
                        if (jj != i) {            // diagonal handled in aggregate
                            int pos = atomicAdd(&g_cnt[jj], 1);
                            if (pos < MAX_DEG) g_list[jj * MAX_DEG + pos] = i;
                        }
                    }
                }
            }
            q = qn;
            c0 = n0; c1 = n1; c2 = n2; c3 = n3;
        }
        return;
    }

    // ================= GEMM (BM=32, 4x4 micro-tile) + attention =================
    __shared__ float xs[BK][BM];       // 2 KB
    __shared__ float ws[BK][C_OUT];    // 8 KB

    int tid  = threadIdx.x;
    int row0 = blockIdx.x * BM;
    int tx = tid & 31;   // channel group: c = tx*4
    int ty = tid >> 5;   // row group: rows ty*4 .. ty*4+3 (warp == fixed ty)

    float acc[4][4];
#pragma unroll
    for (int r = 0; r < 4; r++)
#pragma unroll
        for (int c = 0; c < 4; c++) acc[r][c] = 0.0f;

    for (int k0 = 0; k0 < C_IN; k0 += BK) {
        {   // x tile: 32 rows x 16 k, one float2 per thread
            int r  = tid >> 3;          // 0..31
            int kk = (tid & 7) * 2;     // 0,2,..,14
            float2 v = *reinterpret_cast<const float2*>(
                &x[(row0 + r) * C_IN + k0 + kk]);
            xs[kk + 0][r] = v.x; xs[kk + 1][r] = v.y;
        }
        {   // W tile: 16 k x 128 c, two float4 per thread
            int kk = tid >> 5;              // 0..7
            int c  = (tid & 31) * 4;
            *reinterpret_cast<float4*>(&ws[kk][c]) =
                *reinterpret_cast<const float4*>(&W[(k0 + kk) * C_OUT + c]);
            *reinterpret_cast<float4*>(&ws[kk + 8][c]) =
                *reinterpret_cast<const float4*>(&W[(k0 + kk + 8) * C_OUT + c]);
        }
        __syncthreads();
#pragma unroll
        for (int kk = 0; kk < BK; kk++) {
            float4 b = *reinterpret_cast<const float4*>(&ws[kk][tx * 4]);
#pragma unroll
            for (int r = 0; r < 4; r++) {
                float a = xs[kk][ty * 4 + r];
                acc[r][0] += a * b.x;
                acc[r][1] += a * b.y;
                acc[r][2] += a * b.z;
                acc[r][3] += a * b.w;
            }
        }
        __syncthreads();
    }

    float4 as = *reinterpret_cast<const float4*>(&att_src[tx * 4]);
    float4 ad = *reinterpret_cast<const float4*>(&att_dst[tx * 4]);

#pragma unroll
    for (int r = 0; r < 4; r++) {
        int row = row0 + ty * 4 + r;
        float4 v = make_float4(acc[r][0], acc[r][1], acc[r][2], acc[r][3]);
        *reinterpret_cast<float4*>(&g_h[row * C_OUT + tx * 4]) = v;

        float s = v.x * as.x + v.y * as.y + v.z * as.z + v.w * as.w;
        float d = v.x * ad.x + v.y * ad.y + v.z * ad.z + v.w * ad.w;
#pragma unroll
        for (int o = 16; o > 0; o >>= 1) {
            s += __shfl_xor_sync(0xFFFFFFFFu, s, o);
            d += __shfl_xor_sync(0xFFFFFFFFu, d, o);
        }
        if (tx == 0) { g_asrc[row] = s; g_adst[row] = d; }
    }
}

// ---------------------------------------------------------------------
// Aggregate: one WARP per column. No smem, no block barriers.
// Lane d holds (idx, exp-weight) for edges d, d+32, d+64, d+96 in regs;
// per-edge broadcast via shfl; h-row gathers are per-lane float4
// (coalesced 512B), 4 independent in flight, dual float4 accumulators.
// Resets g_cnt for the next graph replay.
// ---------------------------------------------------------------------
#define FULLM 0xFFFFFFFFu
__global__ __launch_bounds__(256) void aggregate_kernel(
    const float* __restrict__ bias, float* __restrict__ out) {
    int lane = threadIdx.x & 31;
    int j    = blockIdx.x * 8 + (threadIdx.x >> 5);   // column

    int cnt = g_cnt[j];
    if (cnt > MAX_DEG) cnt = MAX_DEG;
    float adst_j = g_adst[j];

    int   idx[4];
    float ew[4];
#pragma unroll
    for (int u = 0; u < 4; u++) {
        int d = lane + u * 32;
        if (d < cnt) {
            int i = g_list[j * MAX_DEG + d];
            idx[u] = i;
            float z = g_asrc[i] + adst_j;
            z = (z > 0.0f) ? z : NEG_SLOPE * z;
            ew[u] = __expf(z);
        } else {
            idx[u] = 0;
            ew[u] = 0.0f;
        }
    }
    if (lane == 0) g_cnt[j] = 0;   // reset for next graph replay

    // self-loop (reference SETS the diagonal to 1 -> always present)
    float zs = g_asrc[j] + adst_j;
    zs = (zs > 0.0f) ? zs : NEG_SLOPE * zs;
    float es = __expf(zs);

    // column sum: warp reduce of all edge weights + self
    float psum = ew[0] + ew[1] + ew[2] + ew[3];
#pragma unroll
    for (int o = 16; o > 0; o >>= 1) psum += __shfl_xor_sync(FULLM, psum, o);
    float inv = 1.0f / (psum + es);

    const float4* hj4 = reinterpret_cast<const float4*>(&g_h[j * C_OUT]);
    float4 h0 = hj4[lane];
    float4 acc0 = make_float4(es * h0.x, es * h0.y, es * h0.z, es * h0.w);
    float4 acc1 = make_float4(0.f, 0.f, 0.f, 0.f);

#pragma unroll
    for (int u = 0; u < 4; u++) {
        int base = u * 32;
        if (base >= cnt) break;
        int m = cnt - base;
        if (m > 32) m = 32;
        int s = 0;
        for (; s + 4 <= m; s += 4) {
            float e0 = __shfl_sync(FULLM, ew[u], s);
            float e1 = __shfl_sync(FULLM, ew[u], s + 1);
            float e2 = __shfl_sync(FULLM, ew[u], s + 2);
            float e3 = __shfl_sync(FULLM, ew[u], s + 3);
            int i0 = __shfl_sync(FULLM, idx[u], s);
            int i1 = __shfl_sync(FULLM, idx[u], s + 1);
            int i2 = __shfl_sync(FULLM, idx[u], s + 2);
            int i3 = __shfl_sync(FULLM, idx[u], s + 3);
            float4 a = reinterpret_cast<const float4*>(&g_h[i0 * C_OUT])[lane];
            float4 b = reinterpret_cast<const float4*>(&g_h[i1 * C_OUT])[lane];
            float4 cc = reinterpret_cast<const float4*>(&g_h[i2 * C_OUT])[lane];
            float4 dd = reinterpret_cast<const float4*>(&g_h[i3 * C_OUT])[lane];
            acc0.x += e0 * a.x;  acc0.y += e0 * a.y;  acc0.z += e0 * a.z;  acc0.w += e0 * a.w;
            acc1.x += e1 * b.x;  acc1.y += e1 * b.y;  acc1.z += e1 * b.z;  acc1.w += e1 * b.w;
            acc0.x += e2 * cc.x; acc0.y += e2 * cc.y; acc0.z += e2 * cc.z; acc0.w += e2 * cc.w;
            acc1.x += e3 * dd.x; acc1.y += e3 * dd.y; acc1.z += e3 * dd.z; acc1.w += e3 * dd.w;
        }
        for (; s < m; s++) {
            float e = __shfl_sync(FULLM, ew[u], s);
            int  i  = __shfl_sync(FULLM, idx[u], s);
            float4 a = reinterpret_cast<const float4*>(&g_h[i * C_OUT])[lane];
            acc0.x += e * a.x; acc0.y += e * a.y; acc0.z += e * a.z; acc0.w += e * a.w;
        }
    }

    float4 bv = reinterpret_cast<const float4*>(bias)[lane];
    float4 o;
    o.x = (acc0.x + acc1.x) * inv + bv.x;
    o.y = (acc0.y + acc1.y) * inv + bv.y;
    o.z = (acc0.z + acc1.z) * inv + bv.z;
    o.w = (acc0.w + acc1.w) * inv + bv.w;
    reinterpret_cast<float4*>(&out[j * C_OUT])[lane] = o;
}

// ---------------------------------------------------------------------
extern "C" void kernel_launch(void* const* d_in, const int* in_sizes, int n_in,
                              void* d_out, int out_size) {
    const float* x       = (const float*)d_in[0];
    const float* adj     = (const float*)d_in[1];
    const float* W       = (const float*)d_in[2];
    const float* att_src = (const float*)d_in[3];
    const float* att_dst = (const float*)d_in[4];
    const float* bias    = (const float*)d_in[5];
    float* out = (float*)d_out;

    fused_front_kernel<<<GEMM_BLOCKS + SCAN_BLOCKS, 256>>>(x, W, adj, att_src, att_dst);
    aggregate_kernel<<<N_NODES / 8, 256>>>(bias, out);
}

// round 7
// speedup vs baseline: 1.0322x; 1.0322x over previous
#include <cuda_runtime.h>
#include <cuda_bf16.h>
#include <math.h>
#include <stdint.h>

#define N_NODES   8192
#define C_IN      256
#define C_OUT     128
#define NEG_SLOPE 0.2f
#define MAX_DEG   128

#define BM 32
#define BK 16
#define GEMM_BLOCKS (N_NODES / BM)     // 256
#define SCAN_BLOCKS 2048

// -------- scratch (__device__ globals; zero-initialized at module load) ----
__device__ float g_h[N_NODES * C_OUT];      // 4 MB, h = x @ W
__device__ float g_asrc[N_NODES];
__device__ float g_adst[N_NODES];
__device__ int   g_cnt[N_NODES];            // per-column degree (excl. self)
__device__ int   g_list[N_NODES * MAX_DEG]; // 4 MB, CSC row lists

// ---------------------------------------------------------------------
// Fused front kernel (R5 configuration — empirically best scan).
//  blocks [0, GEMM_BLOCKS):            h = x@W (4x4 micro-tile) + attn scores
//  blocks [GEMM_BLOCKS, +SCAN_BLOCKS): stream adj once (batch-4 LDG.128)
// g_cnt is zeroed by the previous aggregate launch (zero-init at load).
// ---------------------------------------------------------------------
__global__ __launch_bounds__(256, 6) void fused_front_kernel(
    const float* __restrict__ x, const float* __restrict__ W,
    const float* __restrict__ adj,
    const float* __restrict__ att_src, const float* __restrict__ att_dst) {

    if (blockIdx.x >= GEMM_BLOCKS) {
        // ============ adjacency scan: batch-4 LDG.128 stream ============
        const uint4* a4 = reinterpret_cast<const uint4*>(adj);
        const int tid0   = (blockIdx.x - GEMM_BLOCKS) * 256 + threadIdx.x;
        const int stride = SCAN_BLOCKS * 256;           // 524288
        const int total4 = (N_NODES / 4) * N_NODES;     // 16777216 = 32*stride

        for (int q = tid0; q < total4; q += 4 * stride) {
            uint4 v0 = __ldcs(&a4[q]);
            uint4 v1 = __ldcs(&a4[q + stride]);
            uint4 v2 = __ldcs(&a4[q + 2 * stride]);
            uint4 v3 = __ldcs(&a4[q + 3 * stride]);
            uint4 vv[4] = {v0, v1, v2, v3};
#pragma unroll
            for (int u = 0; u < 4; u++) {
                uint4 v = vv[u];
                if ((v.x | v.y | v.z | v.w) == 0u) continue;
                int Q  = q + u * stride;
                int i  = Q >> 11;                 // row (2048 uint4 per row)
                int j0 = (Q & 2047) << 2;         // first column of the 4
                unsigned int b[4] = {v.x, v.y, v.z, v.w};
#pragma unroll
                for (int t = 0; t < 4; t++) {
                    if (b[t] != 0u) {
                        int jj = j0 + t;
                        if (jj != i) {            // diagonal handled in aggregate
                            int pos = atomicAdd(&g_cnt[jj], 1);
                            if (pos < MAX_DEG) g_list[jj * MAX_DEG + pos] = i;
                        }
                    }
                }
            }
        }
        return;
    }

    // ================= GEMM (BM=32, 4x4 micro-tile) + attention =================
    __shared__ float xs[BK][BM];       // 2 KB
    __shared__ float ws[BK][C_OUT];    // 8 KB

    int tid  = threadIdx.x;
    int row0 = blockIdx.x * BM;
    int tx = tid & 31;   // channel group: c = tx*4
    int ty = tid >> 5;   // row group: rows ty*4 .. ty*4+3 (warp == fixed ty)

    float acc[4][4];
#pragma unroll
    for (int r = 0; r < 4; r++)
#pragma unroll
        for (int c = 0; c < 4; c++) acc[r][c] = 0.0f;

    for (int k0 = 0; k0 < C_IN; k0 += BK) {
        {   // x tile: 32 rows x 16 k, one float2 per thread
            int r  = tid >> 3;          // 0..31
            int kk = (tid & 7) * 2;     // 0,2,..,14
            float2 v = *reinterpret_cast<const float2*>(
                &x[(row0 + r) * C_IN + k0 + kk]);
            xs[kk + 0][r] = v.x; xs[kk + 1][r] = v.y;
        }
        {   // W tile: 16 k x 128 c, two float4 per thread
            int kk = tid >> 5;              // 0..7
            int c  = (tid & 31) * 4;
            *reinterpret_cast<float4*>(&ws[kk][c]) =
                *reinterpret_cast<const float4*>(&W[(k0 + kk) * C_OUT + c]);
            *reinterpret_cast<float4*>(&ws[kk + 8][c]) =
                *reinterpret_cast<const float4*>(&W[(k0 + kk + 8) * C_OUT + c]);
        }
        __syncthreads();
#pragma unroll
        for (int kk = 0; kk < BK; kk++) {
            float4 b = *reinterpret_cast<const float4*>(&ws[kk][tx * 4]);
#pragma unroll
            for (int r = 0; r < 4; r++) {
                float a = xs[kk][ty * 4 + r];
                acc[r][0] += a * b.x;
                acc[r][1] += a * b.y;
                acc[r][2] += a * b.z;
                acc[r][3] += a * b.w;
            }
        }
        __syncthreads();
    }

    float4 as = *reinterpret_cast<const float4*>(&att_src[tx * 4]);
    float4 ad = *reinterpret_cast<const float4*>(&att_dst[tx * 4]);

#pragma unroll
    for (int r = 0; r < 4; r++) {
        int row = row0 + ty * 4 + r;
        float4 v = make_float4(acc[r][0], acc[r][1], acc[r][2], acc[r][3]);
        *reinterpret_cast<float4*>(&g_h[row * C_OUT + tx * 4]) = v;

        float s = v.x * as.x + v.y * as.y + v.z * as.z + v.w * as.w;
        float d = v.x * ad.x + v.y * ad.y + v.z * ad.z + v.w * ad.w;
#pragma unroll
        for (int o = 16; o > 0; o >>= 1) {
            s += __shfl_xor_sync(0xFFFFFFFFu, s, o);
            d += __shfl_xor_sync(0xFFFFFFFFu, d, o);
        }
        if (tx == 0) { g_asrc[row] = s; g_adst[row] = d; }
    }
}

// ---------------------------------------------------------------------
// Aggregate: TWO warps per column (4 columns per 256-thread block).
// Each warp of a pair owns one half of the column's edge list (<=64
// edges -> 2 register-resident (idx, ew) pairs per lane), gathers and
// accumulates its half, then partials combine through smem with one
// __syncthreads(). Doubles warp parallelism and halves every per-warp
// serial latency chain vs the 1-warp version.
// Resets g_cnt for the next graph replay.
// ---------------------------------------------------------------------
#define FULLM 0xFFFFFFFFu
__global__ __launch_bounds__(256) void aggregate_kernel(
    const float* __restrict__ bias, float* __restrict__ out) {
    int warp  = threadIdx.x >> 5;   // 0..7
    int lane  = threadIdx.x & 31;
    int cslot = warp >> 1;          // 0..3 column slot in block
    int half  = warp & 1;           // which half of the edge list
    int j     = blockIdx.x * 4 + cslot;

    __shared__ float4 s_acc[4][32];
    __shared__ float  s_sum[4];

    int cnt = g_cnt[j];
    if (cnt > MAX_DEG) cnt = MAX_DEG;
    float adst_j = g_adst[j];

    // this warp's edge range: [lo, hi)
    int mid = cnt >> 1;
    int lo  = half ? mid : 0;
    int hi  = half ? cnt : mid;
    int myc = hi - lo;              // <= 64

    int   idx[2];
    float ew[2];
#pragma unroll
    for (int u = 0; u < 2; u++) {
        int d = lo + lane + u * 32;
        if (d < hi) {
            int i = g_list[j * MAX_DEG + d];
            idx[u] = i;
            float z = g_asrc[i] + adst_j;
            z = (z > 0.0f) ? z : NEG_SLOPE * z;
            ew[u] = __expf(z);
        } else {
            idx[u] = 0;
            ew[u] = 0.0f;
        }
    }

    // partial edge-weight sum for this half
    float psum = ew[0] + ew[1];
#pragma unroll
    for (int o = 16; o > 0; o >>= 1) psum += __shfl_xor_sync(FULLM, psum, o);

    float4 acc0 = make_float4(0.f, 0.f, 0.f, 0.f);
    float4 acc1 = make_float4(0.f, 0.f, 0.f, 0.f);

#pragma unroll
    for (int u = 0; u < 2; u++) {
        int base = u * 32;
        if (base >= myc) break;
        int m = myc - base;
        if (m > 32) m = 32;
        int s = 0;
        for (; s + 4 <= m; s += 4) {
            float e0 = __shfl_sync(FULLM, ew[u], s);
            float e1 = __shfl_sync(FULLM, ew[u], s + 1);
            float e2 = __shfl_sync(FULLM, ew[u], s + 2);
            float e3 = __shfl_sync(FULLM, ew[u], s + 3);
            int i0 = __shfl_sync(FULLM, idx[u], s);
            int i1 = __shfl_sync(FULLM, idx[u], s + 1);
            int i2 = __shfl_sync(FULLM, idx[u], s + 2);
            int i3 = __shfl_sync(FULLM, idx[u], s + 3);
            float4 a  = reinterpret_cast<const float4*>(&g_h[i0 * C_OUT])[lane];
            float4 b  = reinterpret_cast<const float4*>(&g_h[i1 * C_OUT])[lane];
            float4 cc = reinterpret_cast<const float4*>(&g_h[i2 * C_OUT])[lane];
            float4 dd = reinterpret_cast<const float4*>(&g_h[i3 * C_OUT])[lane];
            acc0.x += e0 * a.x;  acc0.y += e0 * a.y;  acc0.z += e0 * a.z;  acc0.w += e0 * a.w;
            acc1.x += e1 * b.x;  acc1.y += e1 * b.y;  acc1.z += e1 * b.z;  acc1.w += e1 * b.w;
            acc0.x += e2 * cc.x; acc0.y += e2 * cc.y; acc0.z += e2 * cc.z; acc0.w += e2 * cc.w;
            acc1.x += e3 * dd.x; acc1.y += e3 * dd.y; acc1.z += e3 * dd.z; acc1.w += e3 * dd.w;
        }
        for (; s < m; s++) {
            float e = __shfl_sync(FULLM, ew[u], s);
            int  i  = __shfl_sync(FULLM, idx[u], s);
            float4 a = reinterpret_cast<const float4*>(&g_h[i * C_OUT])[lane];
            acc0.x += e * a.x; acc0.y += e * a.y; acc0.z += e * a.z; acc0.w += e * a.w;
        }
    }
    acc0.x += acc1.x; acc0.y += acc1.y; acc0.z += acc1.z; acc0.w += acc1.w;

    if (half == 1) {
        s_acc[cslot][lane] = acc0;
        if (lane == 0) s_sum[cslot] = psum;
    }
    __syncthreads();

    if (half == 0) {
        if (lane == 0) g_cnt[j] = 0;   // reset for next graph replay

        // self-loop (reference SETS the diagonal to 1 -> always present)
        float zs = g_asrc[j] + adst_j;
        zs = (zs > 0.0f) ? zs : NEG_SLOPE * zs;
        float es = __expf(zs);

        float4 hj = reinterpret_cast<const float4*>(&g_h[j * C_OUT])[lane];
        float4 oth = s_acc[cslot][lane];
        float inv = 1.0f / (psum + s_sum[cslot] + es);

        float4 bv = reinterpret_cast<const float4*>(bias)[lane];
        float4 o;
        o.x = (acc0.x + oth.x + es * hj.x) * inv + bv.x;
        o.y = (acc0.y + oth.y + es * hj.y) * inv + bv.y;
        o.z = (acc0.z + oth.z + es * hj.z) * inv + bv.z;
        o.w = (acc0.w + oth.w + es * hj.w) * inv + bv.w;
        reinterpret_cast<float4*>(&out[j * C_OUT])[lane] = o;
    }
}

// ---------------------------------------------------------------------
extern "C" void kernel_launch(void* const* d_in, const int* in_sizes, int n_in,
                              void* d_out, int out_size) {
    const float* x       = (const float*)d_in[0];
    const float* adj     = (const float*)d_in[1];
    const float* W       = (const float*)d_in[2];
    const float* att_src = (const float*)d_in[3];
    const float* att_dst = (const float*)d_in[4];
    const float* bias    = (const float*)d_in[5];
    float* out = (float*)d_out;

    fused_front_kernel<<<GEMM_BLOCKS + SCAN_BLOCKS, 256>>>(x, W, adj, att_src, att_dst);
    aggregate_kernel<<<N_NODES / 4, 256>>>(bias, out);
}

// round 8
// speedup vs baseline: 1.0903x; 1.0563x over previous
#include <cuda_runtime.h>
#include <cuda_bf16.h>
#include <math.h>
#include <stdint.h>

#define N_NODES   8192
#define C_IN      256
#define C_OUT     128
#define NEG_SLOPE 0.2f
#define MAX_DEG   128

#define BM 32
#define BK 16
#define GEMM_BLOCKS (N_NODES / BM)     // 256
#define SCAN_BLOCKS 2048
#define BLOCK_U4    8192               // 128KB contiguous per scan block

// -------- scratch (__device__ globals; zero-initialized at module load) ----
__device__ float g_h[N_NODES * C_OUT];      // 4 MB, h = x @ W
__device__ float g_asrc[N_NODES];
__device__ float g_adst[N_NODES];
__device__ int   g_cnt[N_NODES];            // per-column degree (excl. self)
__device__ int   g_list[N_NODES * MAX_DEG]; // 4 MB, CSC row lists

// ---------------------------------------------------------------------
// Fused front kernel.
//  blocks [0, GEMM_BLOCKS):            h = x@W (4x4 micro-tile) + attn scores
//  blocks [GEMM_BLOCKS, +SCAN_BLOCKS): stream adj once, build CSC lists.
// Scan layout change vs R5: each block owns a CONTIGUOUS 128KB chunk
// (4 adjacency rows); a thread's 4 in-flight LDG.128 span 4KB inside one
// 2MB page, and the block streams its pages sequentially -> DRAM burst
// locality instead of 8MB-strided page thrash.
// g_cnt is zeroed by the previous aggregate launch (zero-init at load).
// ---------------------------------------------------------------------
__global__ __launch_bounds__(256, 6) void fused_front_kernel(
    const float* __restrict__ x, const float* __restrict__ W,
    const float* __restrict__ adj,
    const float* __restrict__ att_src, const float* __restrict__ att_dst) {

    if (blockIdx.x >= GEMM_BLOCKS) {
        // ======= adjacency scan: contiguous chunk, batch-4 LDG.128 =======
        const uint4* a4 = reinterpret_cast<const uint4*>(adj);
        const int sb   = blockIdx.x - GEMM_BLOCKS;
        const int base = sb * BLOCK_U4;          // contiguous 8192-uint4 chunk
        const int tid  = threadIdx.x;

#pragma unroll
        for (int it = 0; it < 8; it++) {
            int qb = base + it * 1024 + tid;     // iter consumes 1024 uint4
            uint4 v0 = __ldcs(&a4[qb]);
            uint4 v1 = __ldcs(&a4[qb + 256]);
            uint4 v2 = __ldcs(&a4[qb + 512]);
            uint4 v3 = __ldcs(&a4[qb + 768]);
            uint4 vv[4] = {v0, v1, v2, v3};
#pragma unroll
            for (int u = 0; u < 4; u++) {
                uint4 v = vv[u];
                if ((v.x | v.y | v.z | v.w) == 0u) continue;
                int Q  = qb + u * 256;
                int i  = Q >> 11;                 // row (2048 uint4 per row)
                int j0 = (Q & 2047) << 2;         // first column of the 4
                unsigned int b[4] = {v.x, v.y, v.z, v.w};
#pragma unroll
                for (int t = 0; t < 4; t++) {
                    if (b[t] != 0u) {
                        int jj = j0 + t;
                        if (jj != i) {            // diagonal handled in aggregate
                            int pos = atomicAdd(&g_cnt[jj], 1);
                            if (pos < MAX_DEG) g_list[jj * MAX_DEG + pos] = i;
                        }
                    }
                }
            }
        }
        return;
    }

    // ================= GEMM (BM=32, 4x4 micro-tile) + attention =================
    __shared__ float xs[BK][BM];       // 2 KB
    __shared__ float ws[BK][C_OUT];    // 8 KB

    int tid  = threadIdx.x;
    int row0 = blockIdx.x * BM;
    int tx = tid & 31;   // channel group: c = tx*4
    int ty = tid >> 5;   // row group: rows ty*4 .. ty*4+3 (warp == fixed ty)

    float acc[4][4];
#pragma unroll
    for (int r = 0; r < 4; r++)
#pragma unroll
        for (int c = 0; c < 4; c++) acc[r][c] = 0.0f;

    for (int k0 = 0; k0 < C_IN; k0 += BK) {
        {   // x tile: 32 rows x 16 k, one float2 per thread
            int r  = tid >> 3;          // 0..31
            int kk = (tid & 7) * 2;     // 0,2,..,14
            float2 v = *reinterpret_cast<const float2*>(
                &x[(row0 + r) * C_IN + k0 + kk]);
            xs[kk + 0][r] = v.x; xs[kk + 1][r] = v.y;
        }
        {   // W tile: 16 k x 128 c, two float4 per thread
            int kk = tid >> 5;              // 0..7
            int c  = (tid & 31) * 4;
            *reinterpret_cast<float4*>(&ws[kk][c]) =
                *reinterpret_cast<const float4*>(&W[(k0 + kk) * C_OUT + c]);
            *reinterpret_cast<float4*>(&ws[kk + 8][c]) =
                *reinterpret_cast<const float4*>(&W[(k0 + kk + 8) * C_OUT + c]);
        }
        __syncthreads();
#pragma unroll
        for (int kk = 0; kk < BK; kk++) {
            float4 b = *reinterpret_cast<const float4*>(&ws[kk][tx * 4]);
#pragma unroll
            for (int r = 0; r < 4; r++) {
                float a = xs[kk][ty * 4 + r];
                acc[r][0] += a * b.x;
                acc[r][1] += a * b.y;
                acc[r][2] += a * b.z;
                acc[r][3] += a * b.w;
            }
        }
        __syncthreads();
    }

    float4 as = *reinterpret_cast<const float4*>(&att_src[tx * 4]);
    float4 ad = *reinterpret_cast<const float4*>(&att_dst[tx * 4]);

#pragma unroll
    for (int r = 0; r < 4; r++) {
        int row = row0 + ty * 4 + r;
        float4 v = make_float4(acc[r][0], acc[r][1], acc[r][2], acc[r][3]);
        *reinterpret_cast<float4*>(&g_h[row * C_OUT + tx * 4]) = v;

        float s = v.x * as.x + v.y * as.y + v.z * as.z + v.w * as.w;
        float d = v.x * ad.x + v.y * ad.y + v.z * ad.z + v.w * ad.w;
#pragma unroll
        for (int o = 16; o > 0; o >>= 1) {
            s += __shfl_xor_sync(0xFFFFFFFFu, s, o);
            d += __shfl_xor_sync(0xFFFFFFFFu, d, o);
        }
        if (tx == 0) { g_asrc[row] = s; g_adst[row] = d; }
    }
}

// ---------------------------------------------------------------------
// Aggregate: one WARP per column (exact R5 version — best measured).
// Lane d holds (idx, exp-weight) for edges d, d+32, d+64, d+96 in regs;
// per-edge broadcast via shfl; h-row gathers are per-lane float4
// (coalesced 512B), 4 independent in flight, dual float4 accumulators.
// Resets g_cnt for the next graph replay.
// ---------------------------------------------------------------------
#define FULLM 0xFFFFFFFFu
__global__ __launch_bounds__(256) void aggregate_kernel(
    const float* __restrict__ bias, float* __restrict__ out) {
    int lane = threadIdx.x & 31;
    int j    = blockIdx.x * 8 + (threadIdx.x >> 5);   // column

    int cnt = g_cnt[j];
    if (cnt > MAX_DEG) cnt = MAX_DEG;
    float adst_j = g_adst[j];

    int   idx[4];
    float ew[4];
#pragma unroll
    for (int u = 0; u < 4; u++) {
        int d = lane + u * 32;
        if (d < cnt) {
            int i = g_list[j * MAX_DEG + d];
            idx[u] = i;
            float z = g_asrc[i] + adst_j;
            z = (z > 0.0f) ? z : NEG_SLOPE * z;
            ew[u] = __expf(z);
        } else {
            idx[u] = 0;
            ew[u] = 0.0f;
        }
    }
    if (lane == 0) g_cnt[j] = 0;   // reset for next graph replay

    // self-loop (reference SETS the diagonal to 1 -> always present)
    float zs = g_asrc[j] + adst_j;
    zs = (zs > 0.0f) ? zs : NEG_SLOPE * zs;
    float es = __expf(zs);

    // column sum: warp reduce of all edge weights + self
    float psum = ew[0] + ew[1] + ew[2] + ew[3];
#pragma unroll
    for (int o = 16; o > 0; o >>= 1) psum += __shfl_xor_sync(FULLM, psum, o);
    float inv = 1.0f / (psum + es);

    const float4* hj4 = reinterpret_cast<const float4*>(&g_h[j * C_OUT]);
    float4 h0 = hj4[lane];
    float4 acc0 = make_float4(es * h0.x, es * h0.y, es * h0.z, es * h0.w);
    float4 acc1 = make_float4(0.f, 0.f, 0.f, 0.f);

#pragma unroll
    for (int u = 0; u < 4; u++) {
        int base = u * 32;
        if (base >= cnt) break;
        int m = cnt - base;
        if (m > 32) m = 32;
        int s = 0;
        for (; s + 4 <= m; s += 4) {
            float e0 = __shfl_sync(FULLM, ew[u], s);
            float e1 = __shfl_sync(FULLM, ew[u], s + 1);
            float e2 = __shfl_sync(FULLM, ew[u], s + 2);
            float e3 = __shfl_sync(FULLM, ew[u], s + 3);
            int i0 = __shfl_sync(FULLM, idx[u], s);
            int i1 = __shfl_sync(FULLM, idx[u], s + 1);
            int i2 = __shfl_sync(FULLM, idx[u], s + 2);
            int i3 = __shfl_sync(FULLM, idx[u], s + 3);
            float4 a = reinterpret_cast<const float4*>(&g_h[i0 * C_OUT])[lane];
            float4 b = reinterpret_cast<const float4*>(&g_h[i1 * C_OUT])[lane];
            float4 cc = reinterpret_cast<const float4*>(&g_h[i2 * C_OUT])[lane];
            float4 dd = reinterpret_cast<const float4*>(&g_h[i3 * C_OUT])[lane];
            acc0.x += e0 * a.x;  acc0.y += e0 * a.y;  acc0.z += e0 * a.z;  acc0.w += e0 * a.w;
            acc1.x += e1 * b.x;  acc1.y += e1 * b.y;  acc1.z += e1 * b.z;  acc1.w += e1 * b.w;
            acc0.x += e2 * cc.x; acc0.y += e2 * cc.y; acc0.z += e2 * cc.z; acc0.w += e2 * cc.w;
            acc1.x += e3 * dd.x; acc1.y += e3 * dd.y; acc1.z += e3 * dd.z; acc1.w += e3 * dd.w;
        }
        for (; s < m; s++) {
            float e = __shfl_sync(FULLM, ew[u], s);
            int  i  = __shfl_sync(FULLM, idx[u], s);
            float4 a = reinterpret_cast<const float4*>(&g_h[i * C_OUT])[lane];
            acc0.x += e * a.x; acc0.y += e * a.y; acc0.z += e * a.z; acc0.w += e * a.w;
        }
    }

    float4 bv = reinterpret_cast<const float4*>(bias)[lane];
    float4 o;
    o.x = (acc0.x + acc1.x) * inv + bv.x;
    o.y = (acc0.y + acc1.y) * inv + bv.y;
    o.z = (acc0.z + acc1.z) * inv + bv.z;
    o.w = (acc0.w + acc1.w) * inv + bv.w;
    reinterpret_cast<float4*>(&out[j * C_OUT])[lane] = o;
}

// ---------------------------------------------------------------------
extern "C" void kernel_launch(void* const* d_in, const int* in_sizes, int n_in,
                              void* d_out, int out_size) {
    const float* x       = (const float*)d_in[0];
    const float* adj     = (const float*)d_in[1];
    const float* W       = (const float*)d_in[2];
    const float* att_src = (const float*)d_in[3];
    const float* att_dst = (const float*)d_in[4];
    const float* bias    = (const float*)d_in[5];
    float* out = (float*)d_out;

    fused_front_kernel<<<GEMM_BLOCKS + SCAN_BLOCKS, 256>>>(x, W, adj, att_src, att_dst);
    aggregate_kernel<<<N_NODES / 8, 256>>>(bias, out);
}